// round 2
// baseline (speedup 1.0000x reference)
#include <cuda_runtime.h>
#include <math.h>
#include <stdint.h>

#define BB 2
#define SS 2048
#define DD 1024
#define HH 16
#define DK 64
#define MROWS (BB*SS)   // 4096

// Scratch (device globals — allocation is forbidden)
__device__ float g_qlin[MROWS*DD];
__device__ float g_klin[MROWS*DD];
__device__ float g_vlin[MROWS*DD];
__device__ float g_qr[BB*HH*SS*DK];
__device__ float g_kr[BB*HH*SS*DK];
__device__ float g_ctx[MROWS*DD];

// ---------------------------------------------------------------------------
// SGEMM: C[M,N] = A[M,K] * W[N,K]^T + bias    (both operands K-contiguous, NT)
// 128x128 block tile, 8x8 per thread, BK=8, 256 threads.
// ---------------------------------------------------------------------------
__global__ __launch_bounds__(256) void sgemm128(
    const float* __restrict__ A, const float* __restrict__ W,
    const float* __restrict__ bias, float* __restrict__ C,
    int M, int N, int K)
{
    __shared__ float As[8][128];
    __shared__ float Ws[8][128];
    const int tid  = threadIdx.x;
    const int bm   = blockIdx.y, bn = blockIdx.x;
    const int lrow = tid >> 1;
    const int lcol = (tid & 1) << 2;
    const float* Ag = A + (size_t)(bm*128 + lrow)*K + lcol;
    const float* Wg = W + (size_t)(bn*128 + lrow)*K + lcol;
    const int tx = tid & 15, ty = tid >> 4;

    float acc[8][8];
    #pragma unroll
    for (int i = 0; i < 8; i++)
        #pragma unroll
        for (int j = 0; j < 8; j++) acc[i][j] = 0.f;

    for (int k0 = 0; k0 < K; k0 += 8) {
        float4 av = *(const float4*)(Ag + k0);
        float4 wv = *(const float4*)(Wg + k0);
        As[lcol+0][lrow] = av.x; As[lcol+1][lrow] = av.y;
        As[lcol+2][lrow] = av.z; As[lcol+3][lrow] = av.w;
        Ws[lcol+0][lrow] = wv.x; Ws[lcol+1][lrow] = wv.y;
        Ws[lcol+2][lrow] = wv.z; Ws[lcol+3][lrow] = wv.w;
        __syncthreads();
        #pragma unroll
        for (int kk = 0; kk < 8; kk++) {
            float a[8], b[8];
            *(float4*)(a)   = *(const float4*)&As[kk][ty*8];
            *(float4*)(a+4) = *(const float4*)&As[kk][ty*8+4];
            *(float4*)(b)   = *(const float4*)&Ws[kk][tx*8];
            *(float4*)(b+4) = *(const float4*)&Ws[kk][tx*8+4];
            #pragma unroll
            for (int i = 0; i < 8; i++)
                #pragma unroll
                for (int j = 0; j < 8; j++)
                    acc[i][j] += a[i]*b[j];
        }
        __syncthreads();
    }

    #pragma unroll
    for (int i = 0; i < 8; i++) {
        int m = bm*128 + ty*8 + i;
        float* Cp = C + (size_t)m*N + bn*128 + tx*8;
        const float* bp = bias + bn*128 + tx*8;
        #pragma unroll
        for (int j = 0; j < 8; j++) Cp[j] = acc[i][j] + bp[j];
    }
}

// ---------------------------------------------------------------------------
// RoPE + [B,S,H,DK] -> [B,H,S,DK] transpose for Q and K.
// One thread per rotation pair (j, j+32). blockIdx.y: 0 = Q, 1 = K.
// ---------------------------------------------------------------------------
__global__ __launch_bounds__(256) void rope_transpose(
    const float* __restrict__ qlin, const float* __restrict__ klin,
    float* __restrict__ qr, float* __restrict__ kr)
{
    const int t = blockIdx.x * 256 + threadIdx.x;    // 0 .. 2^21-1
    const float* src = blockIdx.y ? klin : qlin;
    float*       dst = blockIdx.y ? kr   : qr;
    const int j = t & 31;
    const int s = (t >> 5) & (SS - 1);
    const int h = (t >> 16) & (HH - 1);
    const int b = t >> 20;

    // inv_freq = 10000^(-j/32); angle in fp64 to stay close to exact math
    double inv = exp(-(double)j * 0.28782313662425575);  // ln(10000)/32
    double ang = (double)s * inv;
    double sd, cd;
    sincos(ang, &sd, &cd);
    float c = (float)cd, sn = (float)sd;

    const float* sp = src + ((size_t)(b*SS + s))*DD + h*DK;
    float x1 = sp[j];
    float x2 = sp[j + 32];
    float* dp = dst + (((size_t)(b*HH + h))*SS + s)*DK;
    dp[j]      = x1*c - x2*sn;   // rotate_half: first half gets -x2*sin
    dp[j + 32] = x2*c + x1*sn;
}

// ---------------------------------------------------------------------------
// Flash attention, fp32. One block = one (b,h) and 64 query rows.
// 256 threads as 16x16 grid, 4x4 per thread. Q/K/P stored transposed in smem.
// Pad = 68 floats (multiple of 4) so every row start is 16B-aligned for
// LDS.128 — pad 65 trapped with "misaligned address".
// ---------------------------------------------------------------------------
#define FA_PAD 68
#define FA_SMEM ((64*FA_PAD*3 + 64*64) * 4)

__global__ __launch_bounds__(256) void flash64(
    const float* __restrict__ qr, const float* __restrict__ kr,
    const float* __restrict__ vlin, float* __restrict__ ctx)
{
    extern __shared__ float sm[];
    float* Qt = sm;                 // [64 d][FA_PAD] : Qt[d*FA_PAD + row]
    float* Kt = Qt + 64*FA_PAD;     // [64 d][FA_PAD] : Kt[d*FA_PAD + key]
    float* Pt = Kt + 64*FA_PAD;     // [64 key][FA_PAD] : Pt[c*FA_PAD + row]
    float* Vs = Pt + 64*FA_PAD;     // [64 key][64 d]

    const int tid = threadIdx.x;
    const int qi  = blockIdx.x;            // q tile (0..31)
    const int bh  = blockIdx.y;            // b*H + h (0..31)
    const int b   = bh >> 4, h = bh & 15;
    const int tx  = tid & 15, ty = tid >> 4;

    // Load + transpose Q, pre-scaled by 1/sqrt(DK)
    {
        const float* Qg = qr + ((size_t)bh*SS + qi*64)*DK;
        int r  = tid >> 2;
        int d0 = (tid & 3) << 4;
        #pragma unroll
        for (int dd = 0; dd < 16; dd += 4) {
            float4 v = *(const float4*)(Qg + r*DK + d0 + dd);
            Qt[(d0+dd+0)*FA_PAD + r] = v.x * 0.125f;
            Qt[(d0+dd+1)*FA_PAD + r] = v.y * 0.125f;
            Qt[(d0+dd+2)*FA_PAD + r] = v.z * 0.125f;
            Qt[(d0+dd+3)*FA_PAD + r] = v.w * 0.125f;
        }
    }

    float m_i[4], l_i[4], acc[4][4];
    #pragma unroll
    for (int i = 0; i < 4; i++) {
        m_i[i] = -1e30f; l_i[i] = 0.f;
        #pragma unroll
        for (int j = 0; j < 4; j++) acc[i][j] = 0.f;
    }

    for (int kt = 0; kt <= qi; kt++) {
        __syncthreads();   // protect Kt/Vs against prior iteration readers
        // Load K transposed
        {
            const float* Kg = kr + ((size_t)bh*SS + kt*64)*DK;
            int r  = tid >> 2;
            int d0 = (tid & 3) << 4;
            #pragma unroll
            for (int dd = 0; dd < 16; dd += 4) {
                float4 v = *(const float4*)(Kg + r*DK + d0 + dd);
                Kt[(d0+dd+0)*FA_PAD + r] = v.x;
                Kt[(d0+dd+1)*FA_PAD + r] = v.y;
                Kt[(d0+dd+2)*FA_PAD + r] = v.z;
                Kt[(d0+dd+3)*FA_PAD + r] = v.w;
            }
            // Load V straight (row = key, col = d)
            const float* Vg = vlin + ((size_t)(b*SS + kt*64))*DD + h*DK;
            #pragma unroll
            for (int cc = 0; cc < 16; cc += 4)
                *(float4*)&Vs[r*64 + d0 + cc] = *(const float4*)(Vg + (size_t)r*DD + d0 + cc);
        }
        __syncthreads();

        // Scores: sc[i][j] = sum_d Qt[d][4ty+i] * Kt[d][4tx+j]
        float sc[4][4];
        #pragma unroll
        for (int i = 0; i < 4; i++)
            #pragma unroll
            for (int j = 0; j < 4; j++) sc[i][j] = 0.f;
        #pragma unroll 8
        for (int d = 0; d < 64; d++) {
            float4 qa = *(const float4*)&Qt[d*FA_PAD + ty*4];
            float4 kb = *(const float4*)&Kt[d*FA_PAD + tx*4];
            float a[4] = {qa.x, qa.y, qa.z, qa.w};
            float bv[4] = {kb.x, kb.y, kb.z, kb.w};
            #pragma unroll
            for (int i = 0; i < 4; i++)
                #pragma unroll
                for (int j = 0; j < 4; j++)
                    sc[i][j] += a[i]*bv[j];
        }

        // Causal mask on diagonal tile
        if (kt == qi) {
            #pragma unroll
            for (int i = 0; i < 4; i++)
                #pragma unroll
                for (int j = 0; j < 4; j++)
                    if (tx*4 + j > ty*4 + i) sc[i][j] = -1e30f;
        }

        // Online softmax per row (reduce across the 16 tx lanes)
        #pragma unroll
        for (int i = 0; i < 4; i++) {
            float rm = fmaxf(fmaxf(sc[i][0], sc[i][1]), fmaxf(sc[i][2], sc[i][3]));
            #pragma unroll
            for (int o = 8; o >= 1; o >>= 1)
                rm = fmaxf(rm, __shfl_xor_sync(0xffffffffu, rm, o));
            float mnew = fmaxf(m_i[i], rm);
            float corr = __expf(m_i[i] - mnew);
            m_i[i] = mnew;
            float rs = 0.f;
            #pragma unroll
            for (int j = 0; j < 4; j++) {
                float p = __expf(sc[i][j] - mnew);
                sc[i][j] = p;
                rs += p;
            }
            #pragma unroll
            for (int o = 8; o >= 1; o >>= 1)
                rs += __shfl_xor_sync(0xffffffffu, rs, o);
            l_i[i] = l_i[i]*corr + rs;
            #pragma unroll
            for (int j = 0; j < 4; j++) acc[i][j] *= corr;
        }

        // Stash P transposed: Pt[key][row]
        #pragma unroll
        for (int i = 0; i < 4; i++)
            #pragma unroll
            for (int j = 0; j < 4; j++)
                Pt[(tx*4 + j)*FA_PAD + ty*4 + i] = sc[i][j];
        __syncthreads();

        // O += P @ V : acc[i][j] += sum_c Pt[c][4ty+i] * Vs[c][4tx+j]
        #pragma unroll 8
        for (int c = 0; c < 64; c++) {
            float4 pa = *(const float4*)&Pt[c*FA_PAD + ty*4];
            float4 vb = *(const float4*)&Vs[c*64 + tx*4];
            float p[4] = {pa.x, pa.y, pa.z, pa.w};
            float v[4] = {vb.x, vb.y, vb.z, vb.w};
            #pragma unroll
            for (int i = 0; i < 4; i++)
                #pragma unroll
                for (int j = 0; j < 4; j++)
                    acc[i][j] += p[i]*v[j];
        }
    }

    // Epilogue: normalize and scatter into ctx [B,S,D] (head-interleaved cols)
    #pragma unroll
    for (int i = 0; i < 4; i++) {
        float inv = 1.f / l_i[i];
        int srow = qi*64 + ty*4 + i;
        float4 o;
        o.x = acc[i][0]*inv; o.y = acc[i][1]*inv;
        o.z = acc[i][2]*inv; o.w = acc[i][3]*inv;
        *(float4*)&ctx[((size_t)(b*SS + srow))*DD + h*64 + tx*4] = o;
    }
}

// ---------------------------------------------------------------------------
extern "C" void kernel_launch(void* const* d_in, const int* in_sizes, int n_in,
                              void* d_out, int out_size)
{
    (void)in_sizes; (void)n_in; (void)out_size;
    const float* query = (const float*)d_in[0];
    const float* key   = (const float*)d_in[1];
    const float* value = (const float*)d_in[2];
    // d_in[3] = mask (causal tril) — applied analytically, not read
    const float* Wq = (const float*)d_in[4];
    const float* bq = (const float*)d_in[5];
    const float* Wk = (const float*)d_in[6];
    const float* bk = (const float*)d_in[7];
    const float* Wv = (const float*)d_in[8];
    const float* bv = (const float*)d_in[9];
    const float* Wo = (const float*)d_in[10];
    const float* bo = (const float*)d_in[11];
    float* out = (float*)d_out;

    float *qlin, *klin, *vlin, *qrp, *krp, *ctx;
    cudaGetSymbolAddress((void**)&qlin, g_qlin);
    cudaGetSymbolAddress((void**)&klin, g_klin);
    cudaGetSymbolAddress((void**)&vlin, g_vlin);
    cudaGetSymbolAddress((void**)&qrp,  g_qr);
    cudaGetSymbolAddress((void**)&krp,  g_kr);
    cudaGetSymbolAddress((void**)&ctx,  g_ctx);

    cudaFuncSetAttribute(flash64, cudaFuncAttributeMaxDynamicSharedMemorySize, FA_SMEM);

    dim3 gemmGrid(DD/128, MROWS/128);   // (8, 32)
    sgemm128<<<gemmGrid, 256>>>(query, Wq, bq, qlin, MROWS, DD, DD);
    sgemm128<<<gemmGrid, 256>>>(key,   Wk, bk, klin, MROWS, DD, DD);
    sgemm128<<<gemmGrid, 256>>>(value, Wv, bv, vlin, MROWS, DD, DD);

    dim3 ropeGrid((BB*HH*SS*32)/256, 2);  // (8192, 2)
    rope_transpose<<<ropeGrid, 256>>>(qlin, klin, qrp, krp);

    dim3 faGrid(SS/64, BB*HH);            // (32, 32)
    flash64<<<faGrid, 256, FA_SMEM>>>(qrp, krp, vlin, ctx);

    sgemm128<<<gemmGrid, 256>>>(ctx, Wo, bo, out, MROWS, DD, DD);
}

// round 3
// speedup vs baseline: 1.7577x; 1.7577x over previous
#include <cuda_runtime.h>
#include <cuda_bf16.h>
#include <math.h>
#include <stdint.h>

#define BB 2
#define SS 2048
#define DD 1024
#define HH 16
#define DK 64
#define MROWS (BB*SS)   // 4096

// Scratch (device globals — allocation is forbidden)
__device__ float g_qlin[MROWS*DD];
__device__ float g_klin[MROWS*DD];
__device__ float g_vlin[MROWS*DD];
__device__ float g_qr[BB*HH*SS*DK];
__device__ float g_kr[BB*HH*SS*DK];
__device__ float g_ctx[MROWS*DD];
__device__ float g_cos[SS*32];
__device__ float g_sin[SS*32];

// ---------------------------------------------------------------------------
// RoPE tables: cos/sin[s][j], j = 0..31, computed once in fp64.
// ---------------------------------------------------------------------------
__global__ __launch_bounds__(256) void rope_tables(float* cosT, float* sinT)
{
    const int t = blockIdx.x * 256 + threadIdx.x;   // 0 .. 65535
    const int j = t & 31;
    const int s = t >> 5;
    double inv = exp(-(double)j * 0.28782313662425575);  // ln(10000)/32
    double sd, cd;
    sincos((double)s * inv, &sd, &cd);
    cosT[t] = (float)cd;
    sinT[t] = (float)sd;
}

// ---------------------------------------------------------------------------
// Tensor-core GEMM: C[M,N] = A[M,K] * W[N,K]^T + bias  (NT, fp32 in/out)
// Precision: 3xBF16 split (hi+lo), error ~2^-17 — effectively fp32-grade.
// Block tile 128x128, BK=16, 256 threads = 8 warps of 64x32 warp tiles.
// mma.sync.m16n8k16.bf16, fp32 accumulate.
// ---------------------------------------------------------------------------
#define GP 136   // smem pitch (u32 units): bank = (8*k2 + m) % 32 -> conflict-free frags

__device__ __forceinline__ uint32_t pack_hi(float a, float b, float& ra, float& rb)
{
    __nv_bfloat16 ha = __float2bfloat16(a);
    __nv_bfloat16 hb = __float2bfloat16(b);
    ra = a - __bfloat162float(ha);
    rb = b - __bfloat162float(hb);
    __nv_bfloat162 p;
    p.x = ha; p.y = hb;
    return *reinterpret_cast<uint32_t*>(&p);
}
__device__ __forceinline__ uint32_t pack_lo(float ra, float rb)
{
    __nv_bfloat162 p = __floats2bfloat162_rn(ra, rb);
    return *reinterpret_cast<uint32_t*>(&p);
}

#define MMA_BF16(d, a, b) \
    asm volatile("mma.sync.aligned.m16n8k16.row.col.f32.bf16.bf16.f32 " \
        "{%0,%1,%2,%3}, {%4,%5,%6,%7}, {%8,%9}, {%0,%1,%2,%3};" \
        : "+f"(d[0]), "+f"(d[1]), "+f"(d[2]), "+f"(d[3]) \
        : "r"(a[0]), "r"(a[1]), "r"(a[2]), "r"(a[3]), "r"(b[0]), "r"(b[1]))

__global__ __launch_bounds__(256) void gemm_tc(
    const float* __restrict__ A, const float* __restrict__ W,
    const float* __restrict__ bias, float* __restrict__ C,
    int M, int N, int K)
{
    __shared__ uint32_t Ah[8][GP], Al[8][GP], Wh[8][GP], Wl[8][GP];

    const int tid = threadIdx.x;
    const int bm = blockIdx.y, bn = blockIdx.x;
    const int lane = tid & 31, wid = tid >> 5;
    const int wm = (wid >> 2) * 64;     // warp tile m origin (0 or 64)
    const int wn = (wid & 3) * 32;      // warp tile n origin
    const int qrow = lane >> 2, qk = lane & 3;

    // Loader mapping: row r = tid>>1, k-chunk kc = (tid&1)*8 (8 floats/thread)
    const int r  = tid >> 1;
    const int kc = (tid & 1) << 3;
    const float* Ag = A + (size_t)(bm*128 + r)*K + kc;
    const float* Wg = W + (size_t)(bn*128 + r)*K + kc;
    const int k2b = kc >> 1;   // 0 or 4

    float d[4][4][4];
    #pragma unroll
    for (int mt = 0; mt < 4; mt++)
        #pragma unroll
        for (int nt = 0; nt < 4; nt++)
            #pragma unroll
            for (int i = 0; i < 4; i++) d[mt][nt][i] = 0.f;

    for (int k0 = 0; k0 < K; k0 += 16) {
        // --- stage A & W tiles, split hi/lo bf16, packed k-pairs ---
        {
            float4 v0 = *(const float4*)(Ag + k0);
            float4 v1 = *(const float4*)(Ag + k0 + 4);
            float r0, r1, r2, r3, r4, r5, r6, r7;
            uint32_t h0 = pack_hi(v0.x, v0.y, r0, r1);
            uint32_t h1 = pack_hi(v0.z, v0.w, r2, r3);
            uint32_t h2 = pack_hi(v1.x, v1.y, r4, r5);
            uint32_t h3 = pack_hi(v1.z, v1.w, r6, r7);
            Ah[k2b+0][r] = h0; Ah[k2b+1][r] = h1;
            Ah[k2b+2][r] = h2; Ah[k2b+3][r] = h3;
            Al[k2b+0][r] = pack_lo(r0, r1); Al[k2b+1][r] = pack_lo(r2, r3);
            Al[k2b+2][r] = pack_lo(r4, r5); Al[k2b+3][r] = pack_lo(r6, r7);

            v0 = *(const float4*)(Wg + k0);
            v1 = *(const float4*)(Wg + k0 + 4);
            h0 = pack_hi(v0.x, v0.y, r0, r1);
            h1 = pack_hi(v0.z, v0.w, r2, r3);
            h2 = pack_hi(v1.x, v1.y, r4, r5);
            h3 = pack_hi(v1.z, v1.w, r6, r7);
            Wh[k2b+0][r] = h0; Wh[k2b+1][r] = h1;
            Wh[k2b+2][r] = h2; Wh[k2b+3][r] = h3;
            Wl[k2b+0][r] = pack_lo(r0, r1); Wl[k2b+1][r] = pack_lo(r2, r3);
            Wl[k2b+2][r] = pack_lo(r4, r5); Wl[k2b+3][r] = pack_lo(r6, r7);
        }
        __syncthreads();

        // --- fragment loads (conflict-free: bank = 8*k2 + row) ---
        uint32_t afh[4][4], afl[4][4], bfh[4][2], bfl[4][2];
        #pragma unroll
        for (int mt = 0; mt < 4; mt++) {
            int m0 = wm + mt*16 + qrow;
            #pragma unroll
            for (int i = 0; i < 4; i++) {
                int m  = m0 + ((i & 1) << 3);
                int k2 = qk + ((i >> 1) << 2);
                afh[mt][i] = Ah[k2][m];
                afl[mt][i] = Al[k2][m];
            }
        }
        #pragma unroll
        for (int nt = 0; nt < 4; nt++) {
            int n0 = wn + nt*8 + qrow;
            #pragma unroll
            for (int i = 0; i < 2; i++) {
                bfh[nt][i] = Wh[qk + 4*i][n0];
                bfl[nt][i] = Wl[qk + 4*i][n0];
            }
        }

        // --- 3-pass MMA: hi*hi + hi*lo + lo*hi ---
        #pragma unroll
        for (int mt = 0; mt < 4; mt++)
            #pragma unroll
            for (int nt = 0; nt < 4; nt++) {
                MMA_BF16(d[mt][nt], afh[mt], bfh[nt]);
                MMA_BF16(d[mt][nt], afh[mt], bfl[nt]);
                MMA_BF16(d[mt][nt], afl[mt], bfh[nt]);
            }
        __syncthreads();
    }

    // --- epilogue: d[mt][nt][i] -> C[row][col] + bias ---
    #pragma unroll
    for (int mt = 0; mt < 4; mt++)
        #pragma unroll
        for (int nt = 0; nt < 4; nt++) {
            int col0 = bn*128 + wn + nt*8 + 2*qk;
            float b0 = bias[col0], b1 = bias[col0+1];
            #pragma unroll
            for (int half = 0; half < 2; half++) {
                int row = bm*128 + wm + mt*16 + qrow + 8*half;
                float2 v;
                v.x = d[mt][nt][2*half+0] + b0;
                v.y = d[mt][nt][2*half+1] + b1;
                *(float2*)&C[(size_t)row*N + col0] = v;
            }
        }
}

// ---------------------------------------------------------------------------
// RoPE + [B,S,H,DK] -> [B,H,S,DK] transpose for Q and K. Table-driven.
// ---------------------------------------------------------------------------
__global__ __launch_bounds__(256) void rope_transpose(
    const float* __restrict__ qlin, const float* __restrict__ klin,
    float* __restrict__ qr, float* __restrict__ kr,
    const float* __restrict__ cosT, const float* __restrict__ sinT)
{
    const int t = blockIdx.x * 256 + threadIdx.x;    // 0 .. 2^21-1
    const float* src = blockIdx.y ? klin : qlin;
    float*       dst = blockIdx.y ? kr   : qr;
    const int j = t & 31;
    const int s = (t >> 5) & (SS - 1);
    const int h = (t >> 16) & (HH - 1);
    const int b = t >> 20;

    float c  = cosT[s*32 + j];
    float sn = sinT[s*32 + j];

    const float* sp = src + ((size_t)(b*SS + s))*DD + h*DK;
    float x1 = sp[j];
    float x2 = sp[j + 32];
    float* dp = dst + (((size_t)(b*HH + h))*SS + s)*DK;
    dp[j]      = x1*c - x2*sn;   // rotate_half: first half gets -x2*sin
    dp[j + 32] = x2*c + x1*sn;
}

// ---------------------------------------------------------------------------
// Flash attention, fp32. One block = one (b,h) and 64 query rows.
// 256 threads as 16x16 grid, 4x4 per thread. Q/K/P stored transposed in smem.
// Pad = 68 floats (multiple of 4) so every row start is 16B-aligned.
// ---------------------------------------------------------------------------
#define FA_PAD 68
#define FA_SMEM ((64*FA_PAD*3 + 64*64) * 4)

__global__ __launch_bounds__(256) void flash64(
    const float* __restrict__ qr, const float* __restrict__ kr,
    const float* __restrict__ vlin, float* __restrict__ ctx)
{
    extern __shared__ float sm[];
    float* Qt = sm;                 // [64 d][FA_PAD] : Qt[d*FA_PAD + row]
    float* Kt = Qt + 64*FA_PAD;     // [64 d][FA_PAD] : Kt[d*FA_PAD + key]
    float* Pt = Kt + 64*FA_PAD;     // [64 key][FA_PAD] : Pt[c*FA_PAD + row]
    float* Vs = Pt + 64*FA_PAD;     // [64 key][64 d]

    const int tid = threadIdx.x;
    const int qi  = blockIdx.x;            // q tile (0..31)
    const int bh  = blockIdx.y;            // b*H + h (0..31)
    const int b   = bh >> 4, h = bh & 15;
    const int tx  = tid & 15, ty = tid >> 4;

    // Load + transpose Q, pre-scaled by 1/sqrt(DK)
    {
        const float* Qg = qr + ((size_t)bh*SS + qi*64)*DK;
        int r  = tid >> 2;
        int d0 = (tid & 3) << 4;
        #pragma unroll
        for (int dd = 0; dd < 16; dd += 4) {
            float4 v = *(const float4*)(Qg + r*DK + d0 + dd);
            Qt[(d0+dd+0)*FA_PAD + r] = v.x * 0.125f;
            Qt[(d0+dd+1)*FA_PAD + r] = v.y * 0.125f;
            Qt[(d0+dd+2)*FA_PAD + r] = v.z * 0.125f;
            Qt[(d0+dd+3)*FA_PAD + r] = v.w * 0.125f;
        }
    }

    float m_i[4], l_i[4], acc[4][4];
    #pragma unroll
    for (int i = 0; i < 4; i++) {
        m_i[i] = -1e30f; l_i[i] = 0.f;
        #pragma unroll
        for (int j = 0; j < 4; j++) acc[i][j] = 0.f;
    }

    for (int kt = 0; kt <= qi; kt++) {
        __syncthreads();   // protect Kt/Vs against prior iteration readers
        // Load K transposed
        {
            const float* Kg = kr + ((size_t)bh*SS + kt*64)*DK;
            int r  = tid >> 2;
            int d0 = (tid & 3) << 4;
            #pragma unroll
            for (int dd = 0; dd < 16; dd += 4) {
                float4 v = *(const float4*)(Kg + r*DK + d0 + dd);
                Kt[(d0+dd+0)*FA_PAD + r] = v.x;
                Kt[(d0+dd+1)*FA_PAD + r] = v.y;
                Kt[(d0+dd+2)*FA_PAD + r] = v.z;
                Kt[(d0+dd+3)*FA_PAD + r] = v.w;
            }
            // Load V straight (row = key, col = d)
            const float* Vg = vlin + ((size_t)(b*SS + kt*64))*DD + h*DK;
            #pragma unroll
            for (int cc = 0; cc < 16; cc += 4)
                *(float4*)&Vs[r*64 + d0 + cc] = *(const float4*)(Vg + (size_t)r*DD + d0 + cc);
        }
        __syncthreads();

        // Scores: sc[i][j] = sum_d Qt[d][4ty+i] * Kt[d][4tx+j]
        float sc[4][4];
        #pragma unroll
        for (int i = 0; i < 4; i++)
            #pragma unroll
            for (int j = 0; j < 4; j++) sc[i][j] = 0.f;
        #pragma unroll 8
        for (int d = 0; d < 64; d++) {
            float4 qa = *(const float4*)&Qt[d*FA_PAD + ty*4];
            float4 kb = *(const float4*)&Kt[d*FA_PAD + tx*4];
            float a[4] = {qa.x, qa.y, qa.z, qa.w};
            float bv[4] = {kb.x, kb.y, kb.z, kb.w};
            #pragma unroll
            for (int i = 0; i < 4; i++)
                #pragma unroll
                for (int j = 0; j < 4; j++)
                    sc[i][j] += a[i]*bv[j];
        }

        // Causal mask on diagonal tile
        if (kt == qi) {
            #pragma unroll
            for (int i = 0; i < 4; i++)
                #pragma unroll
                for (int j = 0; j < 4; j++)
                    if (tx*4 + j > ty*4 + i) sc[i][j] = -1e30f;
        }

        // Online softmax per row (reduce across the 16 tx lanes)
        #pragma unroll
        for (int i = 0; i < 4; i++) {
            float rm = fmaxf(fmaxf(sc[i][0], sc[i][1]), fmaxf(sc[i][2], sc[i][3]));
            #pragma unroll
            for (int o = 8; o >= 1; o >>= 1)
                rm = fmaxf(rm, __shfl_xor_sync(0xffffffffu, rm, o));
            float mnew = fmaxf(m_i[i], rm);
            float corr = __expf(m_i[i] - mnew);
            m_i[i] = mnew;
            float rs = 0.f;
            #pragma unroll
            for (int j = 0; j < 4; j++) {
                float p = __expf(sc[i][j] - mnew);
                sc[i][j] = p;
                rs += p;
            }
            #pragma unroll
            for (int o = 8; o >= 1; o >>= 1)
                rs += __shfl_xor_sync(0xffffffffu, rs, o);
            l_i[i] = l_i[i]*corr + rs;
            #pragma unroll
            for (int j = 0; j < 4; j++) acc[i][j] *= corr;
        }

        // Stash P transposed: Pt[key][row]
        #pragma unroll
        for (int i = 0; i < 4; i++)
            #pragma unroll
            for (int j = 0; j < 4; j++)
                Pt[(tx*4 + j)*FA_PAD + ty*4 + i] = sc[i][j];
        __syncthreads();

        // O += P @ V : acc[i][j] += sum_c Pt[c][4ty+i] * Vs[c][4tx+j]
        #pragma unroll 8
        for (int c = 0; c < 64; c++) {
            float4 pa = *(const float4*)&Pt[c*FA_PAD + ty*4];
            float4 vb = *(const float4*)&Vs[c*64 + tx*4];
            float p[4] = {pa.x, pa.y, pa.z, pa.w};
            float v[4] = {vb.x, vb.y, vb.z, vb.w};
            #pragma unroll
            for (int i = 0; i < 4; i++)
                #pragma unroll
                for (int j = 0; j < 4; j++)
                    acc[i][j] += p[i]*v[j];
        }
    }

    // Epilogue: normalize and scatter into ctx [B,S,D] (head-interleaved cols)
    #pragma unroll
    for (int i = 0; i < 4; i++) {
        float inv = 1.f / l_i[i];
        int srow = qi*64 + ty*4 + i;
        float4 o;
        o.x = acc[i][0]*inv; o.y = acc[i][1]*inv;
        o.z = acc[i][2]*inv; o.w = acc[i][3]*inv;
        *(float4*)&ctx[((size_t)(b*SS + srow))*DD + h*64 + tx*4] = o;
    }
}

// ---------------------------------------------------------------------------
extern "C" void kernel_launch(void* const* d_in, const int* in_sizes, int n_in,
                              void* d_out, int out_size)
{
    (void)in_sizes; (void)n_in; (void)out_size;
    const float* query = (const float*)d_in[0];
    const float* key   = (const float*)d_in[1];
    const float* value = (const float*)d_in[2];
    // d_in[3] = mask (causal tril) — applied analytically, not read
    const float* Wq = (const float*)d_in[4];
    const float* bq = (const float*)d_in[5];
    const float* Wk = (const float*)d_in[6];
    const float* bk = (const float*)d_in[7];
    const float* Wv = (const float*)d_in[8];
    const float* bv = (const float*)d_in[9];
    const float* Wo = (const float*)d_in[10];
    const float* bo = (const float*)d_in[11];
    float* out = (float*)d_out;

    float *qlin, *klin, *vlin, *qrp, *krp, *ctx, *cosT, *sinT;
    cudaGetSymbolAddress((void**)&qlin, g_qlin);
    cudaGetSymbolAddress((void**)&klin, g_klin);
    cudaGetSymbolAddress((void**)&vlin, g_vlin);
    cudaGetSymbolAddress((void**)&qrp,  g_qr);
    cudaGetSymbolAddress((void**)&krp,  g_kr);
    cudaGetSymbolAddress((void**)&ctx,  g_ctx);
    cudaGetSymbolAddress((void**)&cosT, g_cos);
    cudaGetSymbolAddress((void**)&sinT, g_sin);

    cudaFuncSetAttribute(flash64, cudaFuncAttributeMaxDynamicSharedMemorySize, FA_SMEM);

    rope_tables<<<SS*32/256, 256>>>(cosT, sinT);

    dim3 gemmGrid(DD/128, MROWS/128);   // (8, 32)
    gemm_tc<<<gemmGrid, 256>>>(query, Wq, bq, qlin, MROWS, DD, DD);
    gemm_tc<<<gemmGrid, 256>>>(key,   Wk, bk, klin, MROWS, DD, DD);
    gemm_tc<<<gemmGrid, 256>>>(value, Wv, bv, vlin, MROWS, DD, DD);

    dim3 ropeGrid((BB*HH*SS*32)/256, 2);  // (8192, 2)
    rope_transpose<<<ropeGrid, 256>>>(qlin, klin, qrp, krp, cosT, sinT);

    dim3 faGrid(SS/64, BB*HH);            // (32, 32)
    flash64<<<faGrid, 256, FA_SMEM>>>(qrp, krp, vlin, ctx);

    gemm_tc<<<gemmGrid, 256>>>(ctx, Wo, bo, out, MROWS, DD, DD);
}